// round 15
// baseline (speedup 1.0000x reference)
#include <cuda_runtime.h>
#include <cuda_fp16.h>
#include <math.h>
#include <stdint.h>

// Problem constants
#define BB 2
#define SS 2048
#define HSIZE 2048
#define NH 16
#define NKV 4
#define HD 128
#define TOK (BB * SS)            // 4096
#define NREP (NH / NKV)          // 4

// Scratch (no cudaMalloc allowed) — all half
__device__ __half g_q[(size_t)TOK * NH * HD];
__device__ __half g_k[(size_t)TOK * NKV * HD];
__device__ __half g_v[(size_t)TOK * NKV * HD];
__device__ __half g_attn[(size_t)TOK * NH * HD];
__device__ __half g_xt[(size_t)TOK * HSIZE];
__device__ __half g_wqr[(size_t)NH * HD * HSIZE];
__device__ __half g_wkr[(size_t)NKV * HD * HSIZE];
__device__ __half g_wvr[(size_t)NKV * HD * HSIZE];
__device__ __half g_wor[(size_t)HSIZE * NH * HD];

// ---------------------------------------------------------------------------
// Helpers
// ---------------------------------------------------------------------------
__device__ __forceinline__ void mma_f16(float* c, const unsigned* a, unsigned b0, unsigned b1) {
    asm volatile(
        "mma.sync.aligned.m16n8k16.row.col.f32.f16.f16.f32 "
        "{%0,%1,%2,%3}, {%4,%5,%6,%7}, {%8,%9}, {%0,%1,%2,%3};"
        : "+f"(c[0]), "+f"(c[1]), "+f"(c[2]), "+f"(c[3])
        : "r"(a[0]), "r"(a[1]), "r"(a[2]), "r"(a[3]), "r"(b0), "r"(b1));
}

__device__ __forceinline__ void ldsm4h(unsigned& r0, unsigned& r1, unsigned& r2, unsigned& r3,
                                       const __half* p) {
    unsigned a = (unsigned)__cvta_generic_to_shared(p);
    asm volatile("ldmatrix.sync.aligned.m8n8.x4.shared.b16 {%0,%1,%2,%3}, [%4];"
                 : "=r"(r0), "=r"(r1), "=r"(r2), "=r"(r3) : "r"(a));
}
__device__ __forceinline__ void ldsm4ht(unsigned& r0, unsigned& r1, unsigned& r2, unsigned& r3,
                                        const __half* p) {
    unsigned a = (unsigned)__cvta_generic_to_shared(p);
    asm volatile("ldmatrix.sync.aligned.m8n8.x4.trans.shared.b16 {%0,%1,%2,%3}, [%4];"
                 : "=r"(r0), "=r"(r1), "=r"(r2), "=r"(r3) : "r"(a));
}

__device__ __forceinline__ void cp16(void* sdst, const void* gsrc) {
    unsigned d = (unsigned)__cvta_generic_to_shared(sdst);
    asm volatile("cp.async.cg.shared.global [%0], [%1], 16;" :: "r"(d), "l"(gsrc));
}
// L1-cached variant: used for GEMM A tiles (shared across co-resident CTAs)
__device__ __forceinline__ void cp16ca(void* sdst, const void* gsrc) {
    unsigned d = (unsigned)__cvta_generic_to_shared(sdst);
    asm volatile("cp.async.ca.shared.global [%0], [%1], 16;" :: "r"(d), "l"(gsrc));
}
#define CP_COMMIT asm volatile("cp.async.commit_group;")
#define CP_WAIT0  asm volatile("cp.async.wait_group 0;")

__device__ __forceinline__ unsigned packh2(float a, float b) {
    __half2 h = __floats2half2_rn(a, b);
    return *(unsigned*)&h;
}

// output store helpers
__device__ __forceinline__ void st2(__half* p, float a, float b) {
    *(__half2*)p = __floats2half2_rn(a, b);
}
__device__ __forceinline__ void st2(float* p, float a, float b) {
    *(float2*)p = make_float2(a, b);
}

// ---------------------------------------------------------------------------
// Merged pre-pass: fp32 -> fp16 for all five tensors in one launch.
// ---------------------------------------------------------------------------
#define N4_X   (TOK * HSIZE / 4)
#define N4_WQ  (NH * HD * HSIZE / 4)
#define N4_WKV (NKV * HD * HSIZE / 4)
#define N4_WO  (HSIZE * NH * HD / 4)
#define N4_TOT (N4_X + N4_WQ + 2 * N4_WKV + N4_WO)

__global__ void to_half_all(const float4* __restrict__ x, const float4* __restrict__ wq,
                            const float4* __restrict__ wk, const float4* __restrict__ wv,
                            const float4* __restrict__ wo,
                            __half2* __restrict__ xt, __half2* __restrict__ wqr,
                            __half2* __restrict__ wkr, __half2* __restrict__ wvr,
                            __half2* __restrict__ wor) {
    int i = blockIdx.x * blockDim.x + threadIdx.x;
    if (i >= N4_TOT) return;
    const float4* src;
    __half2* dst;
    int off;
    if (i < N4_X)                          { src = x;  dst = xt;  off = i; }
    else if (i < N4_X + N4_WQ)             { src = wq; dst = wqr; off = i - N4_X; }
    else if (i < N4_X + N4_WQ + N4_WKV)    { src = wk; dst = wkr; off = i - (N4_X + N4_WQ); }
    else if (i < N4_X + N4_WQ + 2*N4_WKV)  { src = wv; dst = wvr; off = i - (N4_X + N4_WQ + N4_WKV); }
    else                                   { src = wo; dst = wor; off = i - (N4_X + N4_WQ + 2*N4_WKV); }
    float4 v = src[off];
    dst[2 * off]     = __floats2half2_rn(v.x, v.y);
    dst[2 * off + 1] = __floats2half2_rn(v.z, v.w);
}

// ---------------------------------------------------------------------------
// f16 GEMM: C[M,N] = A[M,K] @ B[N,K]^T, half inputs, fp32 accum.
// BM=BN=128, BK=64, 256 threads (8 warps 4x2), 2-stage cp.async, 2 CTAs/SM.
// A tiles loaded with .ca (co-resident CTA shares the same bm tile -> L1 hit).
// ---------------------------------------------------------------------------
#define GSTRIDE 72
#define GSTAGE (128 * GSTRIDE)
#define GEMM_SMEM_BYTES (2 * 2 * GSTAGE * 2)   // 73728

template <typename T>
__device__ __forceinline__ void gemm_core_h(const __half* __restrict__ A,
                                            const __half* __restrict__ B,
                                            T* __restrict__ C,
                                            int Ncols, int K, int bm, int bn,
                                            __half* sm) {
    const int tid = threadIdx.x, lane = tid & 31, warp = tid >> 5;
    const int wm = warp >> 1, wn = warp & 1;
    const int lr = lane & 7, g = lane >> 3;
    const int rowadd = ((g & 1) << 3) + lr;
    const int coladd = (g >> 1) << 3;

    float acc[2][8][4];
#pragma unroll
    for (int mi = 0; mi < 2; mi++)
#pragma unroll
        for (int ni = 0; ni < 8; ni++)
#pragma unroll
            for (int t = 0; t < 4; t++) acc[mi][ni][t] = 0.f;

    const int nIter = K >> 6;

    {
        __half* sA = sm;
        __half* sB = sm + GSTAGE;
#pragma unroll
        for (int i = 0; i < 4; i++) {
            int u = tid + (i << 8);
            int row = u >> 3, seg = u & 7;
            cp16ca(sA + row * GSTRIDE + seg * 8, A + (size_t)(bm + row) * K + seg * 8);
            cp16(sB + row * GSTRIDE + seg * 8, B + (size_t)(bn + row) * K + seg * 8);
        }
        CP_COMMIT;
    }

    for (int it = 0; it < nIter; it++) {
        CP_WAIT0;
        __syncthreads();
        if (it + 1 < nIter) {
            __half* sA = sm + ((it + 1) & 1) * 2 * GSTAGE;
            __half* sB = sA + GSTAGE;
            int k0 = (it + 1) << 6;
#pragma unroll
            for (int i = 0; i < 4; i++) {
                int u = tid + (i << 8);
                int row = u >> 3, seg = u & 7;
                cp16ca(sA + row * GSTRIDE + seg * 8, A + (size_t)(bm + row) * K + k0 + seg * 8);
                cp16(sB + row * GSTRIDE + seg * 8, B + (size_t)(bn + row) * K + k0 + seg * 8);
            }
            CP_COMMIT;
        }
        const __half* sA = sm + (it & 1) * 2 * GSTAGE;
        const __half* sB = sA + GSTAGE;
#pragma unroll
        for (int ks = 0; ks < 4; ks++) {
            unsigned af[2][4];
#pragma unroll
            for (int mi = 0; mi < 2; mi++)
                ldsm4h(af[mi][0], af[mi][1], af[mi][2], af[mi][3],
                       sA + ((wm << 5) + (mi << 4) + rowadd) * GSTRIDE + (ks << 4) + coladd);
#pragma unroll
            for (int np = 0; np < 4; np++) {
                unsigned t0, t1, t2, t3;
                ldsm4h(t0, t1, t2, t3,
                       sB + ((wn << 6) + (np << 4) + rowadd) * GSTRIDE + (ks << 4) + coladd);
#pragma unroll
                for (int mi = 0; mi < 2; mi++) {
                    mma_f16(acc[mi][2 * np], af[mi], t0, t2);
                    mma_f16(acc[mi][2 * np + 1], af[mi], t1, t3);
                }
            }
        }
    }

#pragma unroll
    for (int mi = 0; mi < 2; mi++)
#pragma unroll
        for (int ni = 0; ni < 8; ni++) {
            int r = bm + (wm << 5) + (mi << 4) + (lane >> 2);
            int c = bn + (wn << 6) + (ni << 3) + ((lane & 3) << 1);
            st2(C + (size_t)r * Ncols + c, acc[mi][ni][0], acc[mi][ni][1]);
            st2(C + (size_t)(r + 8) * Ncols + c, acc[mi][ni][2], acc[mi][ni][3]);
        }
}

// Fused QKV projection: grid (24, 32). n-blocks 0-15 -> Q, 16-19 -> K, 20-23 -> V.
__global__ __launch_bounds__(256, 2) void qkv_gemm(const __half* __restrict__ x,
                                                   const __half* __restrict__ wq,
                                                   const __half* __restrict__ wk,
                                                   const __half* __restrict__ wv,
                                                   __half* __restrict__ q,
                                                   __half* __restrict__ k,
                                                   __half* __restrict__ v) {
    extern __shared__ __half smh[];
    int nb = blockIdx.x, bm = blockIdx.y << 7;
    if (nb < 16)       gemm_core_h(x, wq, q, NH * HD,  HSIZE, bm, nb << 7, smh);
    else if (nb < 20)  gemm_core_h(x, wk, k, NKV * HD, HSIZE, bm, (nb - 16) << 7, smh);
    else               gemm_core_h(x, wv, v, NKV * HD, HSIZE, bm, (nb - 20) << 7, smh);
}

__global__ __launch_bounds__(256, 2) void oproj_gemm(const __half* __restrict__ A,
                                                     const __half* __restrict__ B,
                                                     float* __restrict__ C) {
    extern __shared__ __half smh[];
    gemm_core_h(A, B, C, HSIZE, NH * HD, blockIdx.y << 7, blockIdx.x << 7, smh);
}

// ---------------------------------------------------------------------------
// RMS-norm + RoPE for K ONLY (q is fused into the flash prologue).
// One warp per 128-dim row.
// ---------------------------------------------------------------------------
#define QSCALE2 (0.08838834764831845f * 1.44269504088896340736f)

__global__ void rmsk_kernel(const float* __restrict__ cosT,
                            const float* __restrict__ sinT,
                            const float* __restrict__ wkn) {
    const int gwarp = (blockIdx.x * blockDim.x + threadIdx.x) >> 5;
    const int lane = threadIdx.x & 31;
    const int NKROWS = TOK * NKV;
    if (gwarp >= NKROWS) return;

    __half* base = g_k + (size_t)gwarp * HD;
    int s = (gwarp / NKV) % SS;
    const float* w = wkn;

    float v0 = __half2float(base[lane]);
    float v1 = __half2float(base[lane + 32]);
    float v2 = __half2float(base[lane + 64]);
    float v3 = __half2float(base[lane + 96]);
    float ssum = v0 * v0 + v1 * v1 + v2 * v2 + v3 * v3;
#pragma unroll
    for (int o = 16; o > 0; o >>= 1) ssum += __shfl_xor_sync(0xffffffffu, ssum, o);
    float rstd = rsqrtf(ssum * (1.0f / HD) + 1e-6f);

    float n0 = v0 * rstd * w[lane];
    float n1 = v1 * rstd * w[lane + 32];
    float n2 = v2 * rstd * w[lane + 64];
    float n3 = v3 * rstd * w[lane + 96];

    const float* cr = cosT + (size_t)s * HD;
    const float* sr = sinT + (size_t)s * HD;
    float c0 = cr[lane], c1 = cr[lane + 32], c2 = cr[lane + 64], c3 = cr[lane + 96];
    float s0 = sr[lane], s1 = sr[lane + 32], s2 = sr[lane + 64], s3 = sr[lane + 96];

    base[lane]      = __float2half_rn(n0 * c0 - n2 * s0);
    base[lane + 32] = __float2half_rn(n1 * c1 - n3 * s1);
    base[lane + 64] = __float2half_rn(n2 * c2 + n0 * s2);
    base[lane + 96] = __float2half_rn(n3 * c3 + n1 * s3);
}

// ---------------------------------------------------------------------------
// Flash attention (R9 structure) + fused q RMS-norm/RoPE in the prologue
// (fills the K/V tile-0 cp.async wait bubble). f16 mma, warp = 16 q-rows x
// 128 keys, P in registers, double-buffered K/V, one barrier per kt,
// exp2-domain softmax (scale folded into q here).
// ---------------------------------------------------------------------------
#define SH 136
#define FTILE (128 * SH)
#define FLASH_SMEM_BYTES (5 * FTILE * 2)

__global__ __launch_bounds__(256) void flash_kernel(const float* __restrict__ cosT,
                                                    const float* __restrict__ sinT,
                                                    const float* __restrict__ wqn) {
    extern __shared__ __half smh[];
    __half* sQ = smh;
    __half* sK0 = sQ + FTILE;
    __half* sV0 = sK0 + 2 * FTILE;

    const int tid = threadIdx.x, lane = tid & 31, warp = tid >> 5;
    const int lr = lane & 7, g = lane >> 3;
    const int rowadd = ((g & 1) << 3) + lr;
    const int coladd = (g >> 1) << 3;
    const int wq0 = warp << 4;

    const int qt = gridDim.x - 1 - blockIdx.x;
    const int bh = blockIdx.y;
    const int h = bh % NH, b = bh / NH, hkv = h / NREP;
    const int q0 = qt << 7;

    const __half* Qg = g_q + (size_t)b * SS * NH * HD + (size_t)h * HD;
    const __half* Kg = g_k + (size_t)b * SS * NKV * HD + (size_t)hkv * HD;
    const __half* Vg = g_v + (size_t)b * SS * NKV * HD + (size_t)hkv * HD;

    // preload K/V tile 0 -> stage 0
#pragma unroll
    for (int i = 0; i < 8; i++) {
        int u = tid + (i << 8);
        int row = u >> 4, seg = u & 15;
        cp16(sK0 + row * SH + seg * 8, Kg + (size_t)row * (NKV * HD) + seg * 8);
        cp16(sV0 + row * SH + seg * 8, Vg + (size_t)row * (NKV * HD) + seg * 8);
    }
    CP_COMMIT;

    // Q tile (raw, from qkv GEMM)
#pragma unroll
    for (int i = 0; i < 8; i++) {
        int u = tid + (i << 8);
        int row = u >> 4, seg = u & 15;
        *(uint4*)(sQ + row * SH + seg * 8) =
            *(const uint4*)(Qg + (size_t)(q0 + row) * (NH * HD) + seg * 8);
    }
    __syncthreads();   // raw q visible to all

    // Fused q RMS-norm + RoPE + QSCALE2, 2 threads per row (overlaps K/V wait).
    {
        int row = tid >> 1, hf = tid & 1;
        __half* qr = sQ + row * SH + hf * 64;
        const float* cr = cosT + (size_t)(q0 + row) * HD + hf * 64;
        const float* sr = sinT + (size_t)(q0 + row) * HD + hf * 64;
        const float* wr = wqn + hf * 64;

        float ssq = 0.f;
#pragma unroll
        for (int i = 0; i < 32; i++) {
            float2 f = __half22float2(*(__half2*)(qr + 2 * i));
            ssq += f.x * f.x + f.y * f.y;
        }
        ssq += __shfl_xor_sync(0xffffffffu, ssq, 1);
        float rstd = rsqrtf(ssq * (1.0f / HD) + 1e-6f);
        float sgn = hf ? 1.f : -1.f;
#pragma unroll
        for (int i = 0; i < 32; i++) {
            float2 f = __half22float2(*(__half2*)(qr + 2 * i));
            float n0 = f.x * rstd * wr[2 * i];
            float n1 = f.y * rstd * wr[2 * i + 1];
            float p0 = __shfl_xor_sync(0xffffffffu, n0, 1);
            float p1 = __shfl_xor_sync(0xffffffffu, n1, 1);
            float o0 = (n0 * cr[2 * i]     + sgn * p0 * sr[2 * i]) * QSCALE2;
            float o1 = (n1 * cr[2 * i + 1] + sgn * p1 * sr[2 * i + 1]) * QSCALE2;
            *(__half2*)(qr + 2 * i) = __floats2half2_rn(o0, o1);
        }
    }

    float acc[16][4];
#pragma unroll
    for (int ni = 0; ni < 16; ni++)
#pragma unroll
        for (int t = 0; t < 4; t++) acc[ni][t] = 0.f;
    float mrow[2] = {-1e30f, -1e30f}, lrow[2] = {0.f, 0.f};

    for (int kt = 0; kt <= qt; kt++) {
        CP_WAIT0;
        __syncthreads();   // first iter: also publishes normalized sQ
        if (kt < qt) {
            __half* nK = sK0 + ((kt + 1) & 1) * FTILE;
            __half* nV = sV0 + ((kt + 1) & 1) * FTILE;
            size_t krow = (size_t)((kt + 1) << 7);
#pragma unroll
            for (int i = 0; i < 8; i++) {
                int u = tid + (i << 8);
                int row = u >> 4, seg = u & 15;
                cp16(nK + row * SH + seg * 8, Kg + (krow + row) * (NKV * HD) + seg * 8);
                cp16(nV + row * SH + seg * 8, Vg + (krow + row) * (NKV * HD) + seg * 8);
            }
            CP_COMMIT;
        }
        const __half* cK = sK0 + (kt & 1) * FTILE;
        const __half* cV = sV0 + (kt & 1) * FTILE;

        // --- QK^T: s[16 q][128 k] per warp (scores already exp2-scaled) ---
        float s[16][4];
#pragma unroll
        for (int ni = 0; ni < 16; ni++)
#pragma unroll
            for (int t = 0; t < 4; t++) s[ni][t] = 0.f;

#pragma unroll
        for (int kc = 0; kc < 8; kc++) {
            unsigned a[4];
            ldsm4h(a[0], a[1], a[2], a[3],
                   sQ + (wq0 + rowadd) * SH + (kc << 4) + coladd);
#pragma unroll
            for (int np = 0; np < 8; np++) {
                unsigned t0, t1, t2, t3;
                ldsm4h(t0, t1, t2, t3,
                       cK + ((np << 4) + rowadd) * SH + (kc << 4) + coladd);
                mma_f16(s[2 * np], a, t0, t2);
                mma_f16(s[2 * np + 1], a, t1, t3);
            }
        }

        // --- causal mask (diag tile only) ---
        if (kt == qt) {
#pragma unroll
            for (int ni = 0; ni < 16; ni++)
#pragma unroll
                for (int h2 = 0; h2 < 2; h2++) {
                    int rr = wq0 + (lane >> 2) + (h2 << 3);
                    int c0 = (ni << 3) + ((lane & 3) << 1);
                    if (c0 > rr) s[ni][h2 * 2] = -1e30f;
                    if (c0 + 1 > rr) s[ni][h2 * 2 + 1] = -1e30f;
                }
        }

        // --- softmax (registers + quad shuffles, exp2 domain) ---
#pragma unroll
        for (int h2 = 0; h2 < 2; h2++) {
            float mx = -1e30f;
#pragma unroll
            for (int ni = 0; ni < 16; ni++)
                mx = fmaxf(mx, fmaxf(s[ni][h2 * 2], s[ni][h2 * 2 + 1]));
            mx = fmaxf(mx, __shfl_xor_sync(0xffffffffu, mx, 1));
            mx = fmaxf(mx, __shfl_xor_sync(0xffffffffu, mx, 2));
            float mnew = fmaxf(mrow[h2], mx);
            float f = exp2f(mrow[h2] - mnew);
            mrow[h2] = mnew;
            float ls = 0.f;
#pragma unroll
            for (int ni = 0; ni < 16; ni++) {
                float p0 = exp2f(s[ni][h2 * 2] - mnew);
                float p1 = exp2f(s[ni][h2 * 2 + 1] - mnew);
                s[ni][h2 * 2] = p0;
                s[ni][h2 * 2 + 1] = p1;
                ls += p0 + p1;
            }
            ls += __shfl_xor_sync(0xffffffffu, ls, 1);
            ls += __shfl_xor_sync(0xffffffffu, ls, 2);
            lrow[h2] = lrow[h2] * f + ls;
#pragma unroll
            for (int ni = 0; ni < 16; ni++) {
                acc[ni][h2 * 2] *= f;
                acc[ni][h2 * 2 + 1] *= f;
            }
        }

        // pack P -> half (QK C-frag == PV A-frag layout)
        unsigned ph[16][2];
#pragma unroll
        for (int ni = 0; ni < 16; ni++) {
            ph[ni][0] = packh2(s[ni][0], s[ni][1]);
            ph[ni][1] = packh2(s[ni][2], s[ni][3]);
        }

        // --- acc += P @ V (V via ldmatrix.trans) ---
#pragma unroll
        for (int ks = 0; ks < 8; ks++) {
            unsigned a[4] = {ph[2 * ks][0], ph[2 * ks][1],
                             ph[2 * ks + 1][0], ph[2 * ks + 1][1]};
#pragma unroll
            for (int np = 0; np < 8; np++) {
                unsigned t0, t1, t2, t3;
                ldsm4ht(t0, t1, t2, t3,
                        cV + ((ks << 4) + rowadd) * SH + (np << 4) + coladd);
                mma_f16(acc[2 * np], a, t0, t1);
                mma_f16(acc[2 * np + 1], a, t2, t3);
            }
        }
    }

    // epilogue: normalize, store half attn
#pragma unroll
    for (int h2 = 0; h2 < 2; h2++) {
        float inv = 1.f / lrow[h2];
        int rr = wq0 + (lane >> 2) + (h2 << 3);
        size_t base = (size_t)(b * SS + q0 + rr) * (NH * HD) + (size_t)h * HD;
#pragma unroll
        for (int ni = 0; ni < 16; ni++) {
            int c = (ni << 3) + ((lane & 3) << 1);
            *(__half2*)(g_attn + base + c) =
                __floats2half2_rn(acc[ni][h2 * 2] * inv, acc[ni][h2 * 2 + 1] * inv);
        }
    }
}

// ---------------------------------------------------------------------------
// Launch
// ---------------------------------------------------------------------------
extern "C" void kernel_launch(void* const* d_in, const int* in_sizes, int n_in,
                              void* d_out, int out_size) {
    const float* x    = (const float*)d_in[0];
    const float* cosT = (const float*)d_in[1];
    const float* sinT = (const float*)d_in[2];
    // d_in[3] = mask (unused; hard causal is numerically identical)
    const float* wq   = (const float*)d_in[4];
    const float* wk   = (const float*)d_in[5];
    const float* wv   = (const float*)d_in[6];
    const float* wo   = (const float*)d_in[7];
    const float* wqn  = (const float*)d_in[8];
    const float* wkn  = (const float*)d_in[9];
    float* out = (float*)d_out;

    __half *qb, *kb, *vb, *ab, *xt, *wqr, *wkr, *wvr, *wor;
    cudaGetSymbolAddress((void**)&qb, g_q);
    cudaGetSymbolAddress((void**)&kb, g_k);
    cudaGetSymbolAddress((void**)&vb, g_v);
    cudaGetSymbolAddress((void**)&ab, g_attn);
    cudaGetSymbolAddress((void**)&xt, g_xt);
    cudaGetSymbolAddress((void**)&wqr, g_wqr);
    cudaGetSymbolAddress((void**)&wkr, g_wkr);
    cudaGetSymbolAddress((void**)&wvr, g_wvr);
    cudaGetSymbolAddress((void**)&wor, g_wor);

    // fp32 -> fp16 merged prepass
    to_half_all<<<(N4_TOT + 255) / 256, 256>>>(
        (const float4*)x, (const float4*)wq, (const float4*)wk,
        (const float4*)wv, (const float4*)wo,
        (__half2*)xt, (__half2*)wqr, (__half2*)wkr, (__half2*)wvr, (__half2*)wor);

    cudaFuncSetAttribute(qkv_gemm, cudaFuncAttributeMaxDynamicSharedMemorySize,
                         GEMM_SMEM_BYTES);
    cudaFuncSetAttribute(oproj_gemm, cudaFuncAttributeMaxDynamicSharedMemorySize,
                         GEMM_SMEM_BYTES);

    // Fused QKV projection
    qkv_gemm<<<dim3(24, TOK / 128), 256, GEMM_SMEM_BYTES>>>(xt, wqr, wkr, wvr, qb, kb, vb);

    // RMS-norm + RoPE on k only (q fused into flash)
    {
        int total_warps = TOK * NKV;   // 16384
        int blocks = total_warps / 8;
        rmsk_kernel<<<blocks, 256>>>(cosT, sinT, wkn);
    }

    // Flash attention (with fused q norm/rope in prologue)
    cudaFuncSetAttribute(flash_kernel, cudaFuncAttributeMaxDynamicSharedMemorySize,
                         FLASH_SMEM_BYTES);
    flash_kernel<<<dim3(SS / 128, BB * NH), 256, FLASH_SMEM_BYTES>>>(cosT, sinT, wqn);

    // Output projection (fp32 out)
    oproj_gemm<<<dim3(HSIZE / 128, TOK / 128), 256, GEMM_SMEM_BYTES>>>(ab, wor, out);
}

// round 16
// speedup vs baseline: 1.1367x; 1.1367x over previous
#include <cuda_runtime.h>
#include <cuda_fp16.h>
#include <math.h>
#include <stdint.h>

// Problem constants
#define BB 2
#define SS 2048
#define HSIZE 2048
#define NH 16
#define NKV 4
#define HD 128
#define TOK (BB * SS)            // 4096
#define NREP (NH / NKV)          // 4

// Scratch (no cudaMalloc allowed) — all half
__device__ __half g_q[(size_t)TOK * NH * HD];
__device__ __half g_k[(size_t)TOK * NKV * HD];
__device__ __half g_v[(size_t)TOK * NKV * HD];
__device__ __half g_attn[(size_t)TOK * NH * HD];
__device__ __half g_xt[(size_t)TOK * HSIZE];
__device__ __half g_wqr[(size_t)NH * HD * HSIZE];
__device__ __half g_wkr[(size_t)NKV * HD * HSIZE];
__device__ __half g_wvr[(size_t)NKV * HD * HSIZE];
__device__ __half g_wor[(size_t)HSIZE * NH * HD];

// ---------------------------------------------------------------------------
// Helpers
// ---------------------------------------------------------------------------
__device__ __forceinline__ void mma_f16(float* c, const unsigned* a, unsigned b0, unsigned b1) {
    asm volatile(
        "mma.sync.aligned.m16n8k16.row.col.f32.f16.f16.f32 "
        "{%0,%1,%2,%3}, {%4,%5,%6,%7}, {%8,%9}, {%0,%1,%2,%3};"
        : "+f"(c[0]), "+f"(c[1]), "+f"(c[2]), "+f"(c[3])
        : "r"(a[0]), "r"(a[1]), "r"(a[2]), "r"(a[3]), "r"(b0), "r"(b1));
}

__device__ __forceinline__ void ldsm4h(unsigned& r0, unsigned& r1, unsigned& r2, unsigned& r3,
                                       const __half* p) {
    unsigned a = (unsigned)__cvta_generic_to_shared(p);
    asm volatile("ldmatrix.sync.aligned.m8n8.x4.shared.b16 {%0,%1,%2,%3}, [%4];"
                 : "=r"(r0), "=r"(r1), "=r"(r2), "=r"(r3) : "r"(a));
}
__device__ __forceinline__ void ldsm4ht(unsigned& r0, unsigned& r1, unsigned& r2, unsigned& r3,
                                        const __half* p) {
    unsigned a = (unsigned)__cvta_generic_to_shared(p);
    asm volatile("ldmatrix.sync.aligned.m8n8.x4.trans.shared.b16 {%0,%1,%2,%3}, [%4];"
                 : "=r"(r0), "=r"(r1), "=r"(r2), "=r"(r3) : "r"(a));
}

__device__ __forceinline__ void cp16(void* sdst, const void* gsrc) {
    unsigned d = (unsigned)__cvta_generic_to_shared(sdst);
    asm volatile("cp.async.cg.shared.global [%0], [%1], 16;" :: "r"(d), "l"(gsrc));
}
// L1-cached variant: used for GEMM A tiles (co-resident CTA shares the same
// bm tile -> second CTA's loads hit L1)
__device__ __forceinline__ void cp16ca(void* sdst, const void* gsrc) {
    unsigned d = (unsigned)__cvta_generic_to_shared(sdst);
    asm volatile("cp.async.ca.shared.global [%0], [%1], 16;" :: "r"(d), "l"(gsrc));
}
#define CP_COMMIT asm volatile("cp.async.commit_group;")
#define CP_WAIT0  asm volatile("cp.async.wait_group 0;")

__device__ __forceinline__ unsigned packh2(float a, float b) {
    __half2 h = __floats2half2_rn(a, b);
    return *(unsigned*)&h;
}

// output store helpers
__device__ __forceinline__ void st2(__half* p, float a, float b) {
    *(__half2*)p = __floats2half2_rn(a, b);
}
__device__ __forceinline__ void st2(float* p, float a, float b) {
    *(float2*)p = make_float2(a, b);
}

// ---------------------------------------------------------------------------
// Merged pre-pass: fp32 -> fp16 for all five tensors in one launch.
// ---------------------------------------------------------------------------
#define N4_X   (TOK * HSIZE / 4)
#define N4_WQ  (NH * HD * HSIZE / 4)
#define N4_WKV (NKV * HD * HSIZE / 4)
#define N4_WO  (HSIZE * NH * HD / 4)
#define N4_TOT (N4_X + N4_WQ + 2 * N4_WKV + N4_WO)

__global__ void to_half_all(const float4* __restrict__ x, const float4* __restrict__ wq,
                            const float4* __restrict__ wk, const float4* __restrict__ wv,
                            const float4* __restrict__ wo,
                            __half2* __restrict__ xt, __half2* __restrict__ wqr,
                            __half2* __restrict__ wkr, __half2* __restrict__ wvr,
                            __half2* __restrict__ wor) {
    int i = blockIdx.x * blockDim.x + threadIdx.x;
    if (i >= N4_TOT) return;
    const float4* src;
    __half2* dst;
    int off;
    if (i < N4_X)                          { src = x;  dst = xt;  off = i; }
    else if (i < N4_X + N4_WQ)             { src = wq; dst = wqr; off = i - N4_X; }
    else if (i < N4_X + N4_WQ + N4_WKV)    { src = wk; dst = wkr; off = i - (N4_X + N4_WQ); }
    else if (i < N4_X + N4_WQ + 2*N4_WKV)  { src = wv; dst = wvr; off = i - (N4_X + N4_WQ + N4_WKV); }
    else                                   { src = wo; dst = wor; off = i - (N4_X + N4_WQ + 2*N4_WKV); }
    float4 v = src[off];
    dst[2 * off]     = __floats2half2_rn(v.x, v.y);
    dst[2 * off + 1] = __floats2half2_rn(v.z, v.w);
}

// ---------------------------------------------------------------------------
// f16 GEMM: C[M,N] = A[M,K] @ B[N,K]^T, half inputs, fp32 accum.
// BM=BN=128, BK=64, 256 threads (8 warps 4x2), 2-stage cp.async, 2 CTAs/SM.
// A tiles via .ca (L1 reuse across co-resident CTAs), B via .cg.
// ---------------------------------------------------------------------------
#define GSTRIDE 72
#define GSTAGE (128 * GSTRIDE)
#define GEMM_SMEM_BYTES (2 * 2 * GSTAGE * 2)   // 73728

template <typename T>
__device__ __forceinline__ void gemm_core_h(const __half* __restrict__ A,
                                            const __half* __restrict__ B,
                                            T* __restrict__ C,
                                            int Ncols, int K, int bm, int bn,
                                            __half* sm) {
    const int tid = threadIdx.x, lane = tid & 31, warp = tid >> 5;
    const int wm = warp >> 1, wn = warp & 1;
    const int lr = lane & 7, g = lane >> 3;
    const int rowadd = ((g & 1) << 3) + lr;
    const int coladd = (g >> 1) << 3;

    float acc[2][8][4];
#pragma unroll
    for (int mi = 0; mi < 2; mi++)
#pragma unroll
        for (int ni = 0; ni < 8; ni++)
#pragma unroll
            for (int t = 0; t < 4; t++) acc[mi][ni][t] = 0.f;

    const int nIter = K >> 6;

    {
        __half* sA = sm;
        __half* sB = sm + GSTAGE;
#pragma unroll
        for (int i = 0; i < 4; i++) {
            int u = tid + (i << 8);
            int row = u >> 3, seg = u & 7;
            cp16ca(sA + row * GSTRIDE + seg * 8, A + (size_t)(bm + row) * K + seg * 8);
            cp16(sB + row * GSTRIDE + seg * 8, B + (size_t)(bn + row) * K + seg * 8);
        }
        CP_COMMIT;
    }

    for (int it = 0; it < nIter; it++) {
        CP_WAIT0;
        __syncthreads();
        if (it + 1 < nIter) {
            __half* sA = sm + ((it + 1) & 1) * 2 * GSTAGE;
            __half* sB = sA + GSTAGE;
            int k0 = (it + 1) << 6;
#pragma unroll
            for (int i = 0; i < 4; i++) {
                int u = tid + (i << 8);
                int row = u >> 3, seg = u & 7;
                cp16ca(sA + row * GSTRIDE + seg * 8, A + (size_t)(bm + row) * K + k0 + seg * 8);
                cp16(sB + row * GSTRIDE + seg * 8, B + (size_t)(bn + row) * K + k0 + seg * 8);
            }
            CP_COMMIT;
        }
        const __half* sA = sm + (it & 1) * 2 * GSTAGE;
        const __half* sB = sA + GSTAGE;
#pragma unroll
        for (int ks = 0; ks < 4; ks++) {
            unsigned af[2][4];
#pragma unroll
            for (int mi = 0; mi < 2; mi++)
                ldsm4h(af[mi][0], af[mi][1], af[mi][2], af[mi][3],
                       sA + ((wm << 5) + (mi << 4) + rowadd) * GSTRIDE + (ks << 4) + coladd);
#pragma unroll
            for (int np = 0; np < 4; np++) {
                unsigned t0, t1, t2, t3;
                ldsm4h(t0, t1, t2, t3,
                       sB + ((wn << 6) + (np << 4) + rowadd) * GSTRIDE + (ks << 4) + coladd);
#pragma unroll
                for (int mi = 0; mi < 2; mi++) {
                    mma_f16(acc[mi][2 * np], af[mi], t0, t2);
                    mma_f16(acc[mi][2 * np + 1], af[mi], t1, t3);
                }
            }
        }
    }

#pragma unroll
    for (int mi = 0; mi < 2; mi++)
#pragma unroll
        for (int ni = 0; ni < 8; ni++) {
            int r = bm + (wm << 5) + (mi << 4) + (lane >> 2);
            int c = bn + (wn << 6) + (ni << 3) + ((lane & 3) << 1);
            st2(C + (size_t)r * Ncols + c, acc[mi][ni][0], acc[mi][ni][1]);
            st2(C + (size_t)(r + 8) * Ncols + c, acc[mi][ni][2], acc[mi][ni][3]);
        }
}

// Fused QKV projection: grid (24, 32). n-blocks 0-15 -> Q, 16-19 -> K, 20-23 -> V.
__global__ __launch_bounds__(256, 2) void qkv_gemm(const __half* __restrict__ x,
                                                   const __half* __restrict__ wq,
                                                   const __half* __restrict__ wk,
                                                   const __half* __restrict__ wv,
                                                   __half* __restrict__ q,
                                                   __half* __restrict__ k,
                                                   __half* __restrict__ v) {
    extern __shared__ __half smh[];
    int nb = blockIdx.x, bm = blockIdx.y << 7;
    if (nb < 16)       gemm_core_h(x, wq, q, NH * HD,  HSIZE, bm, nb << 7, smh);
    else if (nb < 20)  gemm_core_h(x, wk, k, NKV * HD, HSIZE, bm, (nb - 16) << 7, smh);
    else               gemm_core_h(x, wv, v, NKV * HD, HSIZE, bm, (nb - 20) << 7, smh);
}

__global__ __launch_bounds__(256, 2) void oproj_gemm(const __half* __restrict__ A,
                                                     const __half* __restrict__ B,
                                                     float* __restrict__ C) {
    extern __shared__ __half smh[];
    gemm_core_h(A, B, C, HSIZE, NH * HD, blockIdx.y << 7, blockIdx.x << 7, smh);
}

// ---------------------------------------------------------------------------
// Fused RMS-norm + RoPE on half q/k (fp32 math), one warp per 128-dim row.
// q output pre-multiplied by scale*log2(e): flash softmax runs in the exp2
// domain with no per-score scaling.
// ---------------------------------------------------------------------------
#define QSCALE2 (0.08838834764831845f * 1.44269504088896340736f)

__global__ void rmsrope_kernel(const float* __restrict__ cosT,
                               const float* __restrict__ sinT,
                               const float* __restrict__ wqn,
                               const float* __restrict__ wkn) {
    const int gwarp = (blockIdx.x * blockDim.x + threadIdx.x) >> 5;
    const int lane = threadIdx.x & 31;
    const int NQROWS = TOK * NH;
    const int NKROWS = TOK * NKV;

    __half* base;
    int s;
    const float* w;
    float post;
    if (gwarp < NQROWS) {
        base = g_q + (size_t)gwarp * HD;
        s = (gwarp / NH) % SS;
        w = wqn;
        post = QSCALE2;
    } else {
        int r = gwarp - NQROWS;
        if (r >= NKROWS) return;
        base = g_k + (size_t)r * HD;
        s = (r / NKV) % SS;
        w = wkn;
        post = 1.0f;
    }

    float v0 = __half2float(base[lane]);
    float v1 = __half2float(base[lane + 32]);
    float v2 = __half2float(base[lane + 64]);
    float v3 = __half2float(base[lane + 96]);
    float ssum = v0 * v0 + v1 * v1 + v2 * v2 + v3 * v3;
#pragma unroll
    for (int o = 16; o > 0; o >>= 1) ssum += __shfl_xor_sync(0xffffffffu, ssum, o);
    float rstd = rsqrtf(ssum * (1.0f / HD) + 1e-6f);

    float n0 = v0 * rstd * w[lane];
    float n1 = v1 * rstd * w[lane + 32];
    float n2 = v2 * rstd * w[lane + 64];
    float n3 = v3 * rstd * w[lane + 96];

    const float* cr = cosT + (size_t)s * HD;
    const float* sr = sinT + (size_t)s * HD;
    float c0 = cr[lane], c1 = cr[lane + 32], c2 = cr[lane + 64], c3 = cr[lane + 96];
    float s0 = sr[lane], s1 = sr[lane + 32], s2 = sr[lane + 64], s3 = sr[lane + 96];

    base[lane]      = __float2half_rn((n0 * c0 - n2 * s0) * post);
    base[lane + 32] = __float2half_rn((n1 * c1 - n3 * s1) * post);
    base[lane + 64] = __float2half_rn((n2 * c2 + n0 * s2) * post);
    base[lane + 96] = __float2half_rn((n3 * c3 + n1 * s3) * post);
}

// ---------------------------------------------------------------------------
// Flash attention (R9 structure — converged): f16 mma, warp = 16 q-rows x
// 128 keys, P in registers, double-buffered K/V, one barrier per kt,
// exp2-domain softmax (scale folded into q), mask-only diag pass.
// ---------------------------------------------------------------------------
#define SH 136
#define FTILE (128 * SH)
#define FLASH_SMEM_BYTES (5 * FTILE * 2)

__global__ __launch_bounds__(256) void flash_kernel() {
    extern __shared__ __half smh[];
    __half* sQ = smh;
    __half* sK0 = sQ + FTILE;
    __half* sV0 = sK0 + 2 * FTILE;

    const int tid = threadIdx.x, lane = tid & 31, warp = tid >> 5;
    const int lr = lane & 7, g = lane >> 3;
    const int rowadd = ((g & 1) << 3) + lr;
    const int coladd = (g >> 1) << 3;
    const int wq0 = warp << 4;

    const int qt = gridDim.x - 1 - blockIdx.x;
    const int bh = blockIdx.y;
    const int h = bh % NH, b = bh / NH, hkv = h / NREP;
    const int q0 = qt << 7;

    const __half* Qg = g_q + (size_t)b * SS * NH * HD + (size_t)h * HD;
    const __half* Kg = g_k + (size_t)b * SS * NKV * HD + (size_t)hkv * HD;
    const __half* Vg = g_v + (size_t)b * SS * NKV * HD + (size_t)hkv * HD;

    // preload K/V tile 0 -> stage 0
#pragma unroll
    for (int i = 0; i < 8; i++) {
        int u = tid + (i << 8);
        int row = u >> 4, seg = u & 15;
        cp16(sK0 + row * SH + seg * 8, Kg + (size_t)row * (NKV * HD) + seg * 8);
        cp16(sV0 + row * SH + seg * 8, Vg + (size_t)row * (NKV * HD) + seg * 8);
    }
    CP_COMMIT;

    // Q tile (plain loads, covered by first barrier)
#pragma unroll
    for (int i = 0; i < 8; i++) {
        int u = tid + (i << 8);
        int row = u >> 4, seg = u & 15;
        *(uint4*)(sQ + row * SH + seg * 8) =
            *(const uint4*)(Qg + (size_t)(q0 + row) * (NH * HD) + seg * 8);
    }

    float acc[16][4];
#pragma unroll
    for (int ni = 0; ni < 16; ni++)
#pragma unroll
        for (int t = 0; t < 4; t++) acc[ni][t] = 0.f;
    float mrow[2] = {-1e30f, -1e30f}, lrow[2] = {0.f, 0.f};

    for (int kt = 0; kt <= qt; kt++) {
        CP_WAIT0;
        __syncthreads();
        if (kt < qt) {
            __half* nK = sK0 + ((kt + 1) & 1) * FTILE;
            __half* nV = sV0 + ((kt + 1) & 1) * FTILE;
            size_t krow = (size_t)((kt + 1) << 7);
#pragma unroll
            for (int i = 0; i < 8; i++) {
                int u = tid + (i << 8);
                int row = u >> 4, seg = u & 15;
                cp16(nK + row * SH + seg * 8, Kg + (krow + row) * (NKV * HD) + seg * 8);
                cp16(nV + row * SH + seg * 8, Vg + (krow + row) * (NKV * HD) + seg * 8);
            }
            CP_COMMIT;
        }
        const __half* cK = sK0 + (kt & 1) * FTILE;
        const __half* cV = sV0 + (kt & 1) * FTILE;

        // --- QK^T: s[16 q][128 k] per warp (scores already exp2-scaled) ---
        float s[16][4];
#pragma unroll
        for (int ni = 0; ni < 16; ni++)
#pragma unroll
            for (int t = 0; t < 4; t++) s[ni][t] = 0.f;

#pragma unroll
        for (int kc = 0; kc < 8; kc++) {
            unsigned a[4];
            ldsm4h(a[0], a[1], a[2], a[3],
                   sQ + (wq0 + rowadd) * SH + (kc << 4) + coladd);
#pragma unroll
            for (int np = 0; np < 8; np++) {
                unsigned t0, t1, t2, t3;
                ldsm4h(t0, t1, t2, t3,
                       cK + ((np << 4) + rowadd) * SH + (kc << 4) + coladd);
                mma_f16(s[2 * np], a, t0, t2);
                mma_f16(s[2 * np + 1], a, t1, t3);
            }
        }

        // --- causal mask (diag tile only) ---
        if (kt == qt) {
#pragma unroll
            for (int ni = 0; ni < 16; ni++)
#pragma unroll
                for (int h2 = 0; h2 < 2; h2++) {
                    int rr = wq0 + (lane >> 2) + (h2 << 3);
                    int c0 = (ni << 3) + ((lane & 3) << 1);
                    if (c0 > rr) s[ni][h2 * 2] = -1e30f;
                    if (c0 + 1 > rr) s[ni][h2 * 2 + 1] = -1e30f;
                }
        }

        // --- softmax (registers + quad shuffles, exp2 domain) ---
#pragma unroll
        for (int h2 = 0; h2 < 2; h2++) {
            float mx = -1e30f;
#pragma unroll
            for (int ni = 0; ni < 16; ni++)
                mx = fmaxf(mx, fmaxf(s[ni][h2 * 2], s[ni][h2 * 2 + 1]));
            mx = fmaxf(mx, __shfl_xor_sync(0xffffffffu, mx, 1));
            mx = fmaxf(mx, __shfl_xor_sync(0xffffffffu, mx, 2));
            float mnew = fmaxf(mrow[h2], mx);
            float f = exp2f(mrow[h2] - mnew);
            mrow[h2] = mnew;
            float ls = 0.f;
#pragma unroll
            for (int ni = 0; ni < 16; ni++) {
                float p0 = exp2f(s[ni][h2 * 2] - mnew);
                float p1 = exp2f(s[ni][h2 * 2 + 1] - mnew);
                s[ni][h2 * 2] = p0;
                s[ni][h2 * 2 + 1] = p1;
                ls += p0 + p1;
            }
            ls += __shfl_xor_sync(0xffffffffu, ls, 1);
            ls += __shfl_xor_sync(0xffffffffu, ls, 2);
            lrow[h2] = lrow[h2] * f + ls;
#pragma unroll
            for (int ni = 0; ni < 16; ni++) {
                acc[ni][h2 * 2] *= f;
                acc[ni][h2 * 2 + 1] *= f;
            }
        }

        // pack P -> half (QK C-frag == PV A-frag layout)
        unsigned ph[16][2];
#pragma unroll
        for (int ni = 0; ni < 16; ni++) {
            ph[ni][0] = packh2(s[ni][0], s[ni][1]);
            ph[ni][1] = packh2(s[ni][2], s[ni][3]);
        }

        // --- acc += P @ V (V via ldmatrix.trans) ---
#pragma unroll
        for (int ks = 0; ks < 8; ks++) {
            unsigned a[4] = {ph[2 * ks][0], ph[2 * ks][1],
                             ph[2 * ks + 1][0], ph[2 * ks + 1][1]};
#pragma unroll
            for (int np = 0; np < 8; np++) {
                unsigned t0, t1, t2, t3;
                ldsm4ht(t0, t1, t2, t3,
                        cV + ((ks << 4) + rowadd) * SH + (np << 4) + coladd);
                mma_f16(acc[2 * np], a, t0, t1);
                mma_f16(acc[2 * np + 1], a, t2, t3);
            }
        }
    }

    // epilogue: normalize, store half attn
#pragma unroll
    for (int h2 = 0; h2 < 2; h2++) {
        float inv = 1.f / lrow[h2];
        int rr = wq0 + (lane >> 2) + (h2 << 3);
        size_t base = (size_t)(b * SS + q0 + rr) * (NH * HD) + (size_t)h * HD;
#pragma unroll
        for (int ni = 0; ni < 16; ni++) {
            int c = (ni << 3) + ((lane & 3) << 1);
            *(__half2*)(g_attn + base + c) =
                __floats2half2_rn(acc[ni][h2 * 2] * inv, acc[ni][h2 * 2 + 1] * inv);
        }
    }
}

// ---------------------------------------------------------------------------
// Launch
// ---------------------------------------------------------------------------
extern "C" void kernel_launch(void* const* d_in, const int* in_sizes, int n_in,
                              void* d_out, int out_size) {
    const float* x    = (const float*)d_in[0];
    const float* cosT = (const float*)d_in[1];
    const float* sinT = (const float*)d_in[2];
    // d_in[3] = mask (unused; hard causal is numerically identical)
    const float* wq   = (const float*)d_in[4];
    const float* wk   = (const float*)d_in[5];
    const float* wv   = (const float*)d_in[6];
    const float* wo   = (const float*)d_in[7];
    const float* wqn  = (const float*)d_in[8];
    const float* wkn  = (const float*)d_in[9];
    float* out = (float*)d_out;

    __half *qb, *kb, *vb, *ab, *xt, *wqr, *wkr, *wvr, *wor;
    cudaGetSymbolAddress((void**)&qb, g_q);
    cudaGetSymbolAddress((void**)&kb, g_k);
    cudaGetSymbolAddress((void**)&vb, g_v);
    cudaGetSymbolAddress((void**)&ab, g_attn);
    cudaGetSymbolAddress((void**)&xt, g_xt);
    cudaGetSymbolAddress((void**)&wqr, g_wqr);
    cudaGetSymbolAddress((void**)&wkr, g_wkr);
    cudaGetSymbolAddress((void**)&wvr, g_wvr);
    cudaGetSymbolAddress((void**)&wor, g_wor);

    // fp32 -> fp16 merged prepass
    to_half_all<<<(N4_TOT + 255) / 256, 256>>>(
        (const float4*)x, (const float4*)wq, (const float4*)wk,
        (const float4*)wv, (const float4*)wo,
        (__half2*)xt, (__half2*)wqr, (__half2*)wkr, (__half2*)wvr, (__half2*)wor);

    cudaFuncSetAttribute(qkv_gemm, cudaFuncAttributeMaxDynamicSharedMemorySize,
                         GEMM_SMEM_BYTES);
    cudaFuncSetAttribute(oproj_gemm, cudaFuncAttributeMaxDynamicSharedMemorySize,
                         GEMM_SMEM_BYTES);

    // Fused QKV projection
    qkv_gemm<<<dim3(24, TOK / 128), 256, GEMM_SMEM_BYTES>>>(xt, wqr, wkr, wvr, qb, kb, vb);

    // RMS-norm + RoPE on q (pre-scaled) and k
    {
        int total_warps = TOK * NH + TOK * NKV;
        int blocks = total_warps / 8;
        rmsrope_kernel<<<blocks, 256>>>(cosT, sinT, wqn, wkn);
    }

    // Flash attention
    cudaFuncSetAttribute(flash_kernel, cudaFuncAttributeMaxDynamicSharedMemorySize,
                         FLASH_SMEM_BYTES);
    flash_kernel<<<dim3(SS / 128, BB * NH), 256, FLASH_SMEM_BYTES>>>();

    // Output projection (fp32 out)
    oproj_gemm<<<dim3(HSIZE / 128, TOK / 128), 256, GEMM_SMEM_BYTES>>>(ab, wor, out);
}

// round 17
// speedup vs baseline: 1.1393x; 1.0023x over previous
#include <cuda_runtime.h>
#include <cuda_fp16.h>
#include <math.h>
#include <stdint.h>

// Problem constants
#define BB 2
#define SS 2048
#define HSIZE 2048
#define NH 16
#define NKV 4
#define HD 128
#define TOK (BB * SS)            // 4096
#define NREP (NH / NKV)          // 4

// Scratch (no cudaMalloc allowed) — all half
__device__ __half g_q[(size_t)TOK * NH * HD];
__device__ __half g_k[(size_t)TOK * NKV * HD];
__device__ __half g_v[(size_t)TOK * NKV * HD];
__device__ __half g_attn[(size_t)TOK * NH * HD];
__device__ __half g_xt[(size_t)TOK * HSIZE];
__device__ __half g_wqr[(size_t)NH * HD * HSIZE];
__device__ __half g_wkr[(size_t)NKV * HD * HSIZE];
__device__ __half g_wvr[(size_t)NKV * HD * HSIZE];
__device__ __half g_wor[(size_t)HSIZE * NH * HD];

// ---------------------------------------------------------------------------
// Helpers
// ---------------------------------------------------------------------------
__device__ __forceinline__ void mma_f16(float* c, const unsigned* a, unsigned b0, unsigned b1) {
    asm volatile(
        "mma.sync.aligned.m16n8k16.row.col.f32.f16.f16.f32 "
        "{%0,%1,%2,%3}, {%4,%5,%6,%7}, {%8,%9}, {%0,%1,%2,%3};"
        : "+f"(c[0]), "+f"(c[1]), "+f"(c[2]), "+f"(c[3])
        : "r"(a[0]), "r"(a[1]), "r"(a[2]), "r"(a[3]), "r"(b0), "r"(b1));
}

__device__ __forceinline__ void ldsm4h(unsigned& r0, unsigned& r1, unsigned& r2, unsigned& r3,
                                       const __half* p) {
    unsigned a = (unsigned)__cvta_generic_to_shared(p);
    asm volatile("ldmatrix.sync.aligned.m8n8.x4.shared.b16 {%0,%1,%2,%3}, [%4];"
                 : "=r"(r0), "=r"(r1), "=r"(r2), "=r"(r3) : "r"(a));
}
__device__ __forceinline__ void ldsm4ht(unsigned& r0, unsigned& r1, unsigned& r2, unsigned& r3,
                                        const __half* p) {
    unsigned a = (unsigned)__cvta_generic_to_shared(p);
    asm volatile("ldmatrix.sync.aligned.m8n8.x4.trans.shared.b16 {%0,%1,%2,%3}, [%4];"
                 : "=r"(r0), "=r"(r1), "=r"(r2), "=r"(r3) : "r"(a));
}

__device__ __forceinline__ void cp16(void* sdst, const void* gsrc) {
    unsigned d = (unsigned)__cvta_generic_to_shared(sdst);
    asm volatile("cp.async.cg.shared.global [%0], [%1], 16;" :: "r"(d), "l"(gsrc));
}
// L1-cached variant: used for GEMM A tiles (co-resident CTA shares the same
// bm tile -> second CTA's loads hit L1)
__device__ __forceinline__ void cp16ca(void* sdst, const void* gsrc) {
    unsigned d = (unsigned)__cvta_generic_to_shared(sdst);
    asm volatile("cp.async.ca.shared.global [%0], [%1], 16;" :: "r"(d), "l"(gsrc));
}
#define CP_COMMIT asm volatile("cp.async.commit_group;")
#define CP_WAIT0  asm volatile("cp.async.wait_group 0;")

__device__ __forceinline__ unsigned packh2(float a, float b) {
    __half2 h = __floats2half2_rn(a, b);
    return *(unsigned*)&h;
}
// packed exp2 on two f16 values
__device__ __forceinline__ unsigned ex2h2(unsigned x) {
    unsigned r;
    asm("ex2.approx.f16x2 %0, %1;" : "=r"(r) : "r"(x));
    return r;
}

// output store helpers
__device__ __forceinline__ void st2(__half* p, float a, float b) {
    *(__half2*)p = __floats2half2_rn(a, b);
}
__device__ __forceinline__ void st2(float* p, float a, float b) {
    *(float2*)p = make_float2(a, b);
}

// ---------------------------------------------------------------------------
// Merged pre-pass: fp32 -> fp16 for all five tensors in one launch.
// ---------------------------------------------------------------------------
#define N4_X   (TOK * HSIZE / 4)
#define N4_WQ  (NH * HD * HSIZE / 4)
#define N4_WKV (NKV * HD * HSIZE / 4)
#define N4_WO  (HSIZE * NH * HD / 4)
#define N4_TOT (N4_X + N4_WQ + 2 * N4_WKV + N4_WO)

__global__ void to_half_all(const float4* __restrict__ x, const float4* __restrict__ wq,
                            const float4* __restrict__ wk, const float4* __restrict__ wv,
                            const float4* __restrict__ wo,
                            __half2* __restrict__ xt, __half2* __restrict__ wqr,
                            __half2* __restrict__ wkr, __half2* __restrict__ wvr,
                            __half2* __restrict__ wor) {
    int i = blockIdx.x * blockDim.x + threadIdx.x;
    if (i >= N4_TOT) return;
    const float4* src;
    __half2* dst;
    int off;
    if (i < N4_X)                          { src = x;  dst = xt;  off = i; }
    else if (i < N4_X + N4_WQ)             { src = wq; dst = wqr; off = i - N4_X; }
    else if (i < N4_X + N4_WQ + N4_WKV)    { src = wk; dst = wkr; off = i - (N4_X + N4_WQ); }
    else if (i < N4_X + N4_WQ + 2*N4_WKV)  { src = wv; dst = wvr; off = i - (N4_X + N4_WQ + N4_WKV); }
    else                                   { src = wo; dst = wor; off = i - (N4_X + N4_WQ + 2*N4_WKV); }
    float4 v = src[off];
    dst[2 * off]     = __floats2half2_rn(v.x, v.y);
    dst[2 * off + 1] = __floats2half2_rn(v.z, v.w);
}

// ---------------------------------------------------------------------------
// f16 GEMM: C[M,N] = A[M,K] @ B[N,K]^T, half inputs, fp32 accum.
// BM=BN=128, BK=64, 256 threads (8 warps 4x2), 2-stage cp.async, 2 CTAs/SM.
// A tiles via .ca (L1 reuse across co-resident CTAs), B via .cg.
// ---------------------------------------------------------------------------
#define GSTRIDE 72
#define GSTAGE (128 * GSTRIDE)
#define GEMM_SMEM_BYTES (2 * 2 * GSTAGE * 2)   // 73728

template <typename T>
__device__ __forceinline__ void gemm_core_h(const __half* __restrict__ A,
                                            const __half* __restrict__ B,
                                            T* __restrict__ C,
                                            int Ncols, int K, int bm, int bn,
                                            __half* sm) {
    const int tid = threadIdx.x, lane = tid & 31, warp = tid >> 5;
    const int wm = warp >> 1, wn = warp & 1;
    const int lr = lane & 7, g = lane >> 3;
    const int rowadd = ((g & 1) << 3) + lr;
    const int coladd = (g >> 1) << 3;

    float acc[2][8][4];
#pragma unroll
    for (int mi = 0; mi < 2; mi++)
#pragma unroll
        for (int ni = 0; ni < 8; ni++)
#pragma unroll
            for (int t = 0; t < 4; t++) acc[mi][ni][t] = 0.f;

    const int nIter = K >> 6;

    {
        __half* sA = sm;
        __half* sB = sm + GSTAGE;
#pragma unroll
        for (int i = 0; i < 4; i++) {
            int u = tid + (i << 8);
            int row = u >> 3, seg = u & 7;
            cp16ca(sA + row * GSTRIDE + seg * 8, A + (size_t)(bm + row) * K + seg * 8);
            cp16(sB + row * GSTRIDE + seg * 8, B + (size_t)(bn + row) * K + seg * 8);
        }
        CP_COMMIT;
    }

    for (int it = 0; it < nIter; it++) {
        CP_WAIT0;
        __syncthreads();
        if (it + 1 < nIter) {
            __half* sA = sm + ((it + 1) & 1) * 2 * GSTAGE;
            __half* sB = sA + GSTAGE;
            int k0 = (it + 1) << 6;
#pragma unroll
            for (int i = 0; i < 4; i++) {
                int u = tid + (i << 8);
                int row = u >> 3, seg = u & 7;
                cp16ca(sA + row * GSTRIDE + seg * 8, A + (size_t)(bm + row) * K + k0 + seg * 8);
                cp16(sB + row * GSTRIDE + seg * 8, B + (size_t)(bn + row) * K + k0 + seg * 8);
            }
            CP_COMMIT;
        }
        const __half* sA = sm + (it & 1) * 2 * GSTAGE;
        const __half* sB = sA + GSTAGE;
#pragma unroll
        for (int ks = 0; ks < 4; ks++) {
            unsigned af[2][4];
#pragma unroll
            for (int mi = 0; mi < 2; mi++)
                ldsm4h(af[mi][0], af[mi][1], af[mi][2], af[mi][3],
                       sA + ((wm << 5) + (mi << 4) + rowadd) * GSTRIDE + (ks << 4) + coladd);
#pragma unroll
            for (int np = 0; np < 4; np++) {
                unsigned t0, t1, t2, t3;
                ldsm4h(t0, t1, t2, t3,
                       sB + ((wn << 6) + (np << 4) + rowadd) * GSTRIDE + (ks << 4) + coladd);
#pragma unroll
                for (int mi = 0; mi < 2; mi++) {
                    mma_f16(acc[mi][2 * np], af[mi], t0, t2);
                    mma_f16(acc[mi][2 * np + 1], af[mi], t1, t3);
                }
            }
        }
    }

#pragma unroll
    for (int mi = 0; mi < 2; mi++)
#pragma unroll
        for (int ni = 0; ni < 8; ni++) {
            int r = bm + (wm << 5) + (mi << 4) + (lane >> 2);
            int c = bn + (wn << 6) + (ni << 3) + ((lane & 3) << 1);
            st2(C + (size_t)r * Ncols + c, acc[mi][ni][0], acc[mi][ni][1]);
            st2(C + (size_t)(r + 8) * Ncols + c, acc[mi][ni][2], acc[mi][ni][3]);
        }
}

// Fused QKV projection: grid (24, 32). n-blocks 0-15 -> Q, 16-19 -> K, 20-23 -> V.
__global__ __launch_bounds__(256, 2) void qkv_gemm(const __half* __restrict__ x,
                                                   const __half* __restrict__ wq,
                                                   const __half* __restrict__ wk,
                                                   const __half* __restrict__ wv,
                                                   __half* __restrict__ q,
                                                   __half* __restrict__ k,
                                                   __half* __restrict__ v) {
    extern __shared__ __half smh[];
    int nb = blockIdx.x, bm = blockIdx.y << 7;
    if (nb < 16)       gemm_core_h(x, wq, q, NH * HD,  HSIZE, bm, nb << 7, smh);
    else if (nb < 20)  gemm_core_h(x, wk, k, NKV * HD, HSIZE, bm, (nb - 16) << 7, smh);
    else               gemm_core_h(x, wv, v, NKV * HD, HSIZE, bm, (nb - 20) << 7, smh);
}

__global__ __launch_bounds__(256, 2) void oproj_gemm(const __half* __restrict__ A,
                                                     const __half* __restrict__ B,
                                                     float* __restrict__ C) {
    extern __shared__ __half smh[];
    gemm_core_h(A, B, C, HSIZE, NH * HD, blockIdx.y << 7, blockIdx.x << 7, smh);
}

// ---------------------------------------------------------------------------
// Fused RMS-norm + RoPE on half q/k (fp32 math), one warp per 128-dim row.
// q output pre-multiplied by scale*log2(e): flash softmax runs in the exp2
// domain with no per-score scaling.
// ---------------------------------------------------------------------------
#define QSCALE2 (0.08838834764831845f * 1.44269504088896340736f)

__global__ void rmsrope_kernel(const float* __restrict__ cosT,
                               const float* __restrict__ sinT,
                               const float* __restrict__ wqn,
                               const float* __restrict__ wkn) {
    const int gwarp = (blockIdx.x * blockDim.x + threadIdx.x) >> 5;
    const int lane = threadIdx.x & 31;
    const int NQROWS = TOK * NH;
    const int NKROWS = TOK * NKV;

    __half* base;
    int s;
    const float* w;
    float post;
    if (gwarp < NQROWS) {
        base = g_q + (size_t)gwarp * HD;
        s = (gwarp / NH) % SS;
        w = wqn;
        post = QSCALE2;
    } else {
        int r = gwarp - NQROWS;
        if (r >= NKROWS) return;
        base = g_k + (size_t)r * HD;
        s = (r / NKV) % SS;
        w = wkn;
        post = 1.0f;
    }

    float v0 = __half2float(base[lane]);
    float v1 = __half2float(base[lane + 32]);
    float v2 = __half2float(base[lane + 64]);
    float v3 = __half2float(base[lane + 96]);
    float ssum = v0 * v0 + v1 * v1 + v2 * v2 + v3 * v3;
#pragma unroll
    for (int o = 16; o > 0; o >>= 1) ssum += __shfl_xor_sync(0xffffffffu, ssum, o);
    float rstd = rsqrtf(ssum * (1.0f / HD) + 1e-6f);

    float n0 = v0 * rstd * w[lane];
    float n1 = v1 * rstd * w[lane + 32];
    float n2 = v2 * rstd * w[lane + 64];
    float n3 = v3 * rstd * w[lane + 96];

    const float* cr = cosT + (size_t)s * HD;
    const float* sr = sinT + (size_t)s * HD;
    float c0 = cr[lane], c1 = cr[lane + 32], c2 = cr[lane + 64], c3 = cr[lane + 96];
    float s0 = sr[lane], s1 = sr[lane + 32], s2 = sr[lane + 64], s3 = sr[lane + 96];

    base[lane]      = __float2half_rn((n0 * c0 - n2 * s0) * post);
    base[lane + 32] = __float2half_rn((n1 * c1 - n3 * s1) * post);
    base[lane + 64] = __float2half_rn((n2 * c2 + n0 * s2) * post);
    base[lane + 96] = __float2half_rn((n3 * c3 + n1 * s3) * post);
}

// ---------------------------------------------------------------------------
// Flash attention: f16 mma, warp = 16 q-rows x 128 keys, P in registers,
// double-buffered K/V, one barrier per kt, exp2-domain softmax with packed
// ex2.approx.f16x2 exponentials (output == PV A-fragment; no separate pack).
// ---------------------------------------------------------------------------
#define SH 136
#define FTILE (128 * SH)
#define FLASH_SMEM_BYTES (5 * FTILE * 2)

__global__ __launch_bounds__(256) void flash_kernel() {
    extern __shared__ __half smh[];
    __half* sQ = smh;
    __half* sK0 = sQ + FTILE;
    __half* sV0 = sK0 + 2 * FTILE;

    const int tid = threadIdx.x, lane = tid & 31, warp = tid >> 5;
    const int lr = lane & 7, g = lane >> 3;
    const int rowadd = ((g & 1) << 3) + lr;
    const int coladd = (g >> 1) << 3;
    const int wq0 = warp << 4;

    const int qt = gridDim.x - 1 - blockIdx.x;
    const int bh = blockIdx.y;
    const int h = bh % NH, b = bh / NH, hkv = h / NREP;
    const int q0 = qt << 7;

    const __half* Qg = g_q + (size_t)b * SS * NH * HD + (size_t)h * HD;
    const __half* Kg = g_k + (size_t)b * SS * NKV * HD + (size_t)hkv * HD;
    const __half* Vg = g_v + (size_t)b * SS * NKV * HD + (size_t)hkv * HD;

    // preload K/V tile 0 -> stage 0
#pragma unroll
    for (int i = 0; i < 8; i++) {
        int u = tid + (i << 8);
        int row = u >> 4, seg = u & 15;
        cp16(sK0 + row * SH + seg * 8, Kg + (size_t)row * (NKV * HD) + seg * 8);
        cp16(sV0 + row * SH + seg * 8, Vg + (size_t)row * (NKV * HD) + seg * 8);
    }
    CP_COMMIT;

    // Q tile (plain loads, covered by first barrier)
#pragma unroll
    for (int i = 0; i < 8; i++) {
        int u = tid + (i << 8);
        int row = u >> 4, seg = u & 15;
        *(uint4*)(sQ + row * SH + seg * 8) =
            *(const uint4*)(Qg + (size_t)(q0 + row) * (NH * HD) + seg * 8);
    }

    float acc[16][4];
#pragma unroll
    for (int ni = 0; ni < 16; ni++)
#pragma unroll
        for (int t = 0; t < 4; t++) acc[ni][t] = 0.f;
    float mrow[2] = {-1e30f, -1e30f}, lrow[2] = {0.f, 0.f};

    for (int kt = 0; kt <= qt; kt++) {
        CP_WAIT0;
        __syncthreads();
        if (kt < qt) {
            __half* nK = sK0 + ((kt + 1) & 1) * FTILE;
            __half* nV = sV0 + ((kt + 1) & 1) * FTILE;
            size_t krow = (size_t)((kt + 1) << 7);
#pragma unroll
            for (int i = 0; i < 8; i++) {
                int u = tid + (i << 8);
                int row = u >> 4, seg = u & 15;
                cp16(nK + row * SH + seg * 8, Kg + (krow + row) * (NKV * HD) + seg * 8);
                cp16(nV + row * SH + seg * 8, Vg + (krow + row) * (NKV * HD) + seg * 8);
            }
            CP_COMMIT;
        }
        const __half* cK = sK0 + (kt & 1) * FTILE;
        const __half* cV = sV0 + (kt & 1) * FTILE;

        // --- QK^T: s[16 q][128 k] per warp (scores already exp2-scaled) ---
        float s[16][4];
#pragma unroll
        for (int ni = 0; ni < 16; ni++)
#pragma unroll
            for (int t = 0; t < 4; t++) s[ni][t] = 0.f;

#pragma unroll
        for (int kc = 0; kc < 8; kc++) {
            unsigned a[4];
            ldsm4h(a[0], a[1], a[2], a[3],
                   sQ + (wq0 + rowadd) * SH + (kc << 4) + coladd);
#pragma unroll
            for (int np = 0; np < 8; np++) {
                unsigned t0, t1, t2, t3;
                ldsm4h(t0, t1, t2, t3,
                       cK + ((np << 4) + rowadd) * SH + (kc << 4) + coladd);
                mma_f16(s[2 * np], a, t0, t2);
                mma_f16(s[2 * np + 1], a, t1, t3);
            }
        }

        // --- causal mask (diag tile only) ---
        if (kt == qt) {
#pragma unroll
            for (int ni = 0; ni < 16; ni++)
#pragma unroll
                for (int h2 = 0; h2 < 2; h2++) {
                    int rr = wq0 + (lane >> 2) + (h2 << 3);
                    int c0 = (ni << 3) + ((lane & 3) << 1);
                    if (c0 > rr) s[ni][h2 * 2] = -1e30f;
                    if (c0 + 1 > rr) s[ni][h2 * 2 + 1] = -1e30f;
                }
        }

        // --- softmax: packed f16x2 exponentials (straight-line) ---
        unsigned ph[16][2];
#pragma unroll
        for (int h2 = 0; h2 < 2; h2++) {
            float mx = -1e30f;
#pragma unroll
            for (int ni = 0; ni < 16; ni++)
                mx = fmaxf(mx, fmaxf(s[ni][h2 * 2], s[ni][h2 * 2 + 1]));
            mx = fmaxf(mx, __shfl_xor_sync(0xffffffffu, mx, 1));
            mx = fmaxf(mx, __shfl_xor_sync(0xffffffffu, mx, 2));
            float mnew = fmaxf(mrow[h2], mx);
            float f = exp2f(mrow[h2] - mnew);
            mrow[h2] = mnew;
            float ls = 0.f;
#pragma unroll
            for (int ni = 0; ni < 16; ni++) {
                unsigned pe = ex2h2(packh2(s[ni][h2 * 2] - mnew,
                                           s[ni][h2 * 2 + 1] - mnew));
                ph[ni][h2] = pe;
                float2 pf = __half22float2(*(__half2*)&pe);
                ls += pf.x + pf.y;
            }
            ls += __shfl_xor_sync(0xffffffffu, ls, 1);
            ls += __shfl_xor_sync(0xffffffffu, ls, 2);
            lrow[h2] = lrow[h2] * f + ls;
#pragma unroll
            for (int ni = 0; ni < 16; ni++) {
                acc[ni][h2 * 2] *= f;
                acc[ni][h2 * 2 + 1] *= f;
            }
        }

        // --- acc += P @ V (V via ldmatrix.trans) ---
#pragma unroll
        for (int ks = 0; ks < 8; ks++) {
            unsigned a[4] = {ph[2 * ks][0], ph[2 * ks][1],
                             ph[2 * ks + 1][0], ph[2 * ks + 1][1]};
#pragma unroll
            for (int np = 0; np < 8; np++) {
                unsigned t0, t1, t2, t3;
                ldsm4ht(t0, t1, t2, t3,
                        cV + ((ks << 4) + rowadd) * SH + (np << 4) + coladd);
                mma_f16(acc[2 * np], a, t0, t1);
                mma_f16(acc[2 * np + 1], a, t2, t3);
            }
        }
    }

    // epilogue: normalize, store half attn
#pragma unroll
    for (int h2 = 0; h2 < 2; h2++) {
        float inv = 1.f / lrow[h2];
        int rr = wq0 + (lane >> 2) + (h2 << 3);
        size_t base = (size_t)(b * SS + q0 + rr) * (NH * HD) + (size_t)h * HD;
#pragma unroll
        for (int ni = 0; ni < 16; ni++) {
            int c = (ni << 3) + ((lane & 3) << 1);
            *(__half2*)(g_attn + base + c) =
                __floats2half2_rn(acc[ni][h2 * 2] * inv, acc[ni][h2 * 2 + 1] * inv);
        }
    }
}

// ---------------------------------------------------------------------------
// Launch
// ---------------------------------------------------------------------------
extern "C" void kernel_launch(void* const* d_in, const int* in_sizes, int n_in,
                              void* d_out, int out_size) {
    const float* x    = (const float*)d_in[0];
    const float* cosT = (const float*)d_in[1];
    const float* sinT = (const float*)d_in[2];
    // d_in[3] = mask (unused; hard causal is numerically identical)
    const float* wq   = (const float*)d_in[4];
    const float* wk   = (const float*)d_in[5];
    const float* wv   = (const float*)d_in[6];
    const float* wo   = (const float*)d_in[7];
    const float* wqn  = (const float*)d_in[8];
    const float* wkn  = (const float*)d_in[9];
    float* out = (float*)d_out;

    __half *qb, *kb, *vb, *ab, *xt, *wqr, *wkr, *wvr, *wor;
    cudaGetSymbolAddress((void**)&qb, g_q);
    cudaGetSymbolAddress((void**)&kb, g_k);
    cudaGetSymbolAddress((void**)&vb, g_v);
    cudaGetSymbolAddress((void**)&ab, g_attn);
    cudaGetSymbolAddress((void**)&xt, g_xt);
    cudaGetSymbolAddress((void**)&wqr, g_wqr);
    cudaGetSymbolAddress((void**)&wkr, g_wkr);
    cudaGetSymbolAddress((void**)&wvr, g_wvr);
    cudaGetSymbolAddress((void**)&wor, g_wor);

    // fp32 -> fp16 merged prepass
    to_half_all<<<(N4_TOT + 255) / 256, 256>>>(
        (const float4*)x, (const float4*)wq, (const float4*)wk,
        (const float4*)wv, (const float4*)wo,
        (__half2*)xt, (__half2*)wqr, (__half2*)wkr, (__half2*)wvr, (__half2*)wor);

    cudaFuncSetAttribute(qkv_gemm, cudaFuncAttributeMaxDynamicSharedMemorySize,
                         GEMM_SMEM_BYTES);
    cudaFuncSetAttribute(oproj_gemm, cudaFuncAttributeMaxDynamicSharedMemorySize,
                         GEMM_SMEM_BYTES);

    // Fused QKV projection
    qkv_gemm<<<dim3(24, TOK / 128), 256, GEMM_SMEM_BYTES>>>(xt, wqr, wkr, wvr, qb, kb, vb);

    // RMS-norm + RoPE on q (pre-scaled) and k
    {
        int total_warps = TOK * NH + TOK * NKV;
        int blocks = total_warps / 8;
        rmsrope_kernel<<<blocks, 256>>>(cosT, sinT, wqn, wkn);
    }

    // Flash attention
    cudaFuncSetAttribute(flash_kernel, cudaFuncAttributeMaxDynamicSharedMemorySize,
                         FLASH_SMEM_BYTES);
    flash_kernel<<<dim3(SS / 128, BB * NH), 256, FLASH_SMEM_BYTES>>>();

    // Output projection (fp32 out)
    oproj_gemm<<<dim3(HSIZE / 128, TOK / 128), 256, GEMM_SMEM_BYTES>>>(ab, wor, out);
}